// round 9
// baseline (speedup 1.0000x reference)
#include <cuda_runtime.h>
#include <cstdint>

#define VOCAB 256
#define D 512
#define A 64
#define BB 8
#define LL 2048
#define LN_EPS 1e-5f

// ---------------- scratch (device globals; no allocations) ----------------
__device__ float4 g_hP[128 * VOCAB];       // packed h: [d/4][v] -> h[v][4d..4d+3]
__device__ float g_q[VOCAB * A];
__device__ float g_kT[A * VOCAB];
__device__ float g_gate[VOCAB];
__device__ float g_logit[VOCAB * VOCAB];
__device__ float g_vprob[VOCAB * VOCAB];
__device__ float g_score[VOCAB * VOCAB];
__device__ float g_cnt[BB * VOCAB];

// ---------------- reduction helpers ----------------
__device__ __forceinline__ float warpSum(float v) {
    #pragma unroll
    for (int o = 16; o > 0; o >>= 1) v += __shfl_xor_sync(0xFFFFFFFFu, v, o);
    return v;
}
__device__ __forceinline__ float warpMax(float v) {
    #pragma unroll
    for (int o = 16; o > 0; o >>= 1) v = fmaxf(v, __shfl_xor_sync(0xFFFFFFFFu, v, o));
    return v;
}
__device__ __forceinline__ float blockSum256(float v, float* sh) {
    int w = threadIdx.x >> 5, l = threadIdx.x & 31;
    v = warpSum(v);
    if (l == 0) sh[w] = v;
    __syncthreads();
    if (w == 0) {
        float x = (l < 8) ? sh[l] : 0.f;
        x = warpSum(x);
        if (l == 0) sh[0] = x;
    }
    __syncthreads();
    float r = sh[0];
    __syncthreads();
    return r;
}
__device__ __forceinline__ float blockMax256(float v, float* sh) {
    int w = threadIdx.x >> 5, l = threadIdx.x & 31;
    v = warpMax(v);
    if (l == 0) sh[w] = v;
    __syncthreads();
    if (w == 0) {
        float x = (l < 8) ? sh[l] : -1e30f;
        x = warpMax(x);
        if (l == 0) sh[0] = x;
    }
    __syncthreads();
    float r = sh[0];
    __syncthreads();
    return r;
}

// ---------------- k_hn: histogram (blocks 0-7) + LN once (blocks 8-39) ----
__global__ void __launch_bounds__(256)
k_hn(const int* __restrict__ tokens, const int* __restrict__ plen,
     const float* __restrict__ E,
     const float* __restrict__ eg, const float* __restrict__ eb,
     const float* __restrict__ fg, const float* __restrict__ fb) {
    int tid = threadIdx.x, w = tid >> 5, l = tid & 31;

    if (blockIdx.x < 8) {
        int b = blockIdx.x;
        __shared__ int c[VOCAB];
        c[tid] = 0;
        __syncthreads();
        int P = plen[b];
        #pragma unroll
        for (int it = 0; it < 8; it++) {
            int i = it * 256 + tid;
            int tk = tokens[b * LL + i];
            if (i < P && tk != 0) atomicAdd(&c[tk & 255], 1);
        }
        __syncthreads();
        g_cnt[b * VOCAB + tid] = (float)c[tid];
        return;
    }

    // LN for row v = (blk-8)*8 + w, stored packed-transposed to g_hP
    int v = (blockIdx.x - 8) * 8 + w;
    const float4* E4 = (const float4*)E;
    float4 ef[4];
    #pragma unroll
    for (int j = 0; j < 4; j++) ef[j] = E4[v * 128 + l + 32 * j];
    float s = 0.f;
    #pragma unroll
    for (int j = 0; j < 4; j++) s += ef[j].x + ef[j].y + ef[j].z + ef[j].w;
    float mu = warpSum(s) * (1.f / D);
    float vv = 0.f;
    #pragma unroll
    for (int j = 0; j < 4; j++) {
        ef[j].x -= mu; ef[j].y -= mu; ef[j].z -= mu; ef[j].w -= mu;
        vv += ef[j].x * ef[j].x + ef[j].y * ef[j].y
            + ef[j].z * ef[j].z + ef[j].w * ef[j].w;
    }
    float inv = rsqrtf(warpSum(vv) * (1.f / D) + LN_EPS);
    {
        const float4* G = (const float4*)eg;
        const float4* Bv = (const float4*)eb;
        #pragma unroll
        for (int j = 0; j < 4; j++) {
            float4 g4 = G[l + 32 * j], b4 = Bv[l + 32 * j];
            ef[j].x = ef[j].x * inv * g4.x + b4.x;
            ef[j].y = ef[j].y * inv * g4.y + b4.y;
            ef[j].z = ef[j].z * inv * g4.z + b4.z;
            ef[j].w = ef[j].w * inv * g4.w + b4.w;
        }
    }
    s = 0.f;
    #pragma unroll
    for (int j = 0; j < 4; j++) s += ef[j].x + ef[j].y + ef[j].z + ef[j].w;
    mu = warpSum(s) * (1.f / D);
    vv = 0.f;
    #pragma unroll
    for (int j = 0; j < 4; j++) {
        ef[j].x -= mu; ef[j].y -= mu; ef[j].z -= mu; ef[j].w -= mu;
        vv += ef[j].x * ef[j].x + ef[j].y * ef[j].y
            + ef[j].z * ef[j].z + ef[j].w * ef[j].w;
    }
    inv = rsqrtf(warpSum(vv) * (1.f / D) + LN_EPS);
    {
        const float4* G = (const float4*)fg;
        const float4* Bv = (const float4*)fb;
        #pragma unroll
        for (int j = 0; j < 4; j++) {
            float4 g4 = G[l + 32 * j], b4 = Bv[l + 32 * j];
            float4 hv;
            hv.x = ef[j].x * inv * g4.x + b4.x;
            hv.y = ef[j].y * inv * g4.y + b4.y;
            hv.z = ef[j].z * inv * g4.z + b4.z;
            hv.w = ef[j].w * inv * g4.w + b4.w;
            g_hP[(l + 32 * j) * VOCAB + v] = hv;   // packed-transposed
        }
    }
}

// ---------------- k_gemm: C[v][o] = h[v] . w[o], thread-dense -------------
// grid.x = 49 o-groups * 2 v-halves. block 256 threads:
//   v = vh*128 + (tid & 127),  oo = tid >> 7 (2 o-subgroups of 4)
// o index: [0,256) logits, [256,320) q, [320,384) kT, 384 gate
__global__ void __launch_bounds__(256)
k_gemm(const float* __restrict__ E,
       const float* __restrict__ qw, const float* __restrict__ qb,
       const float* __restrict__ kw, const float* __restrict__ kb,
       const float* __restrict__ gw, const float* __restrict__ gb) {
    int tid = threadIdx.x;
    int og = blockIdx.x >> 1, vh = blockIdx.x & 1;
    int v = vh * 128 + (tid & 127);
    int oo = tid >> 7;

    __shared__ __align__(16) float ws[8][D];   // 16 KB: this block's 8 weight rows

    // stage 8 weight rows into smem (warp w loads row w)
    {
        int w = tid >> 5, l = tid & 31;
        int o = og * 8 + w;
        int oe = (o <= 384) ? o : 384;
        const float* wr;
        if (oe < 256)      wr = E + oe * D;
        else if (oe < 320) wr = qw + (oe - 256) * D;
        else if (oe < 384) wr = kw + (oe - 320) * D;
        else               wr = gw;
        const float4* wr4 = (const float4*)wr;
        float4* ws4 = (float4*)ws[w];
        #pragma unroll
        for (int jj = 0; jj < 4; jj++) ws4[l + 32 * jj] = wr4[l + 32 * jj];
    }
    __syncthreads();

    float acc0 = 0.f, acc1 = 0.f, acc2 = 0.f, acc3 = 0.f;
    const float4* ws4_0 = (const float4*)ws[oo * 4 + 0];
    const float4* ws4_1 = (const float4*)ws[oo * 4 + 1];
    const float4* ws4_2 = (const float4*)ws[oo * 4 + 2];
    const float4* ws4_3 = (const float4*)ws[oo * 4 + 3];

    #pragma unroll 4
    for (int d4 = 0; d4 < 128; d4++) {
        float4 h4 = g_hP[d4 * VOCAB + v];
        float4 w0 = ws4_0[d4], w1 = ws4_1[d4], w2 = ws4_2[d4], w3 = ws4_3[d4];
        acc0 += w0.x * h4.x + w0.y * h4.y + w0.z * h4.z + w0.w * h4.w;
        acc1 += w1.x * h4.x + w1.y * h4.y + w1.z * h4.z + w1.w * h4.w;
        acc2 += w2.x * h4.x + w2.y * h4.y + w2.z * h4.z + w2.w * h4.w;
        acc3 += w3.x * h4.x + w3.y * h4.y + w3.z * h4.z + w3.w * h4.w;
    }

    float accs[4] = {acc0, acc1, acc2, acc3};
    #pragma unroll
    for (int i = 0; i < 4; i++) {
        int o = og * 8 + oo * 4 + i;
        if (o > 384) continue;
        float s = accs[i];
        if (o < 256)      g_logit[v * VOCAB + o] = s;
        else if (o < 320) g_q[v * A + (o - 256)] = s + qb[o - 256];
        else if (o < 384) g_kT[(o - 320) * VOCAB + v] = s + kb[o - 320];
        else              g_gate[v] = 1.f / (1.f + __expf(-(s + gb[0])));
    }
}

// ---------------- k_sm: vocab softmax + score row per qv ------------------
__global__ void __launch_bounds__(256)
k_sm() {
    int qv = blockIdx.x, tid = threadIdx.x;
    __shared__ float red[8];
    __shared__ float qs[A];
    float lo = g_logit[qv * VOCAB + tid];
    if (tid < A) qs[tid] = g_q[qv * A + tid];
    __syncthreads();                 // qs visible to ALL warps before reading
    float s = 0.f;
    #pragma unroll
    for (int d = 0; d < A; d++) s += qs[d] * g_kT[d * VOCAB + tid];
    g_score[qv * VOCAB + tid] = s * 0.125f;
    float m = blockMax256(lo, red);
    float e = __expf(lo - m);
    float Z = blockSum256(e, red);
    g_vprob[qv * VOCAB + tid] = e * __frcp_rn(Z);
}

// ---------------- k_write: AT/LM compute + streaming writer ---------------
__global__ void __launch_bounds__(256)
k_write(const int* __restrict__ tokens, const int* __restrict__ plen,
        float* __restrict__ out, int has_gate, int has_attn) {
    int b = blockIdx.y, t0 = blockIdx.x * 16, tid = threadIdx.x;
    int w = tid >> 5, l = tid & 31;
    __shared__ __align__(16) int toks[LL];
    __shared__ float lut[16][VOCAB];
    __shared__ float scnt[VOCAB];
    __shared__ int qvs[16];

    scnt[tid] = g_cnt[b * VOCAB + tid];
    const int4* tg = (const int4*)(tokens + b * LL);
    int4* ts = (int4*)toks;
    ts[tid] = tg[tid];
    ts[tid + 256] = tg[tid + 256];
    __syncthreads();
    if (tid < 16) qvs[tid] = toks[t0 + tid] & 255;
    __syncthreads();

    // ---- AT rows: warp w computes rows w and w+8 (shuffles only) ----
    #pragma unroll
    for (int jj = 0; jj < 2; jj++) {
        int j = w + jj * 8;
        int qv = qvs[j];
        float sv[8], cf[8];
        float mx = -1e30f;
        #pragma unroll
        for (int m = 0; m < 8; m++) {
            int v = l + 32 * m;
            sv[m] = g_score[qv * VOCAB + v];
            cf[m] = scnt[v];
            mx = fmaxf(mx, cf[m] > 0.f ? sv[m] : -1e30f);
        }
        mx = warpMax(mx);
        float ex[8], z = 0.f;
        #pragma unroll
        for (int m = 0; m < 8; m++) {
            ex[m] = __expf(sv[m] - mx);
            z += cf[m] * ex[m];
        }
        z = warpSum(z);
        float invz = __frcp_rn(z);
        #pragma unroll
        for (int m = 0; m < 8; m++) {
            int v = l + 32 * m;
            float at = ex[m] * invz;
            if (v == 0) at = 0.f;            // PAD column masked
            lut[j][v] = at;
        }
    }
    __syncthreads();

    int P = plen[b];
    float* out_lm   = out;
    float* out_gate = out + (size_t)BB * LL * VOCAB;
    float* out_attn = out_gate + (size_t)BB * LL;

    if (has_gate && tid < 16) out_gate[b * LL + t0 + tid] = g_gate[qvs[tid]];

    // ---- LM: thread = column, 16 rows ----
    float cn = scnt[tid];
    #pragma unroll
    for (int j = 0; j < 16; j++) {
        int qv = qvs[j];
        float gt = g_gate[qv];
        float pv = g_vprob[qv * VOCAB + tid];
        float mixed = gt * pv + (1.f - gt) * (cn * lut[j][tid]);
        __stcs(out_lm + ((size_t)(b * LL + t0 + j)) * VOCAB + tid,
               __logf(fmaxf(mixed, 1e-12f)));
    }

    // ---- attn streaming ----
    if (has_attn) {
        #pragma unroll
        for (int j = 0; j < 16; j++) {
            float4* orow = (float4*)(out_attn + ((size_t)(b * LL + t0 + j)) * LL);
            #pragma unroll
            for (int k2 = 0; k2 < 2; k2++) {
                int sb = (k2 * 256 + tid) * 4;
                int4 tk = *(const int4*)&toks[sb];
                float4 o;
                o.x = (sb + 0 < P) ? lut[j][tk.x & 255] : 0.f;
                o.y = (sb + 1 < P) ? lut[j][tk.y & 255] : 0.f;
                o.z = (sb + 2 < P) ? lut[j][tk.z & 255] : 0.f;
                o.w = (sb + 3 < P) ? lut[j][tk.w & 255] : 0.f;
                __stcs(orow + k2 * 256 + tid, o);
            }
        }
    }
}

// ---------------- launch ----------------
extern "C" void kernel_launch(void* const* d_in, const int* in_sizes, int n_in,
                              void* d_out, int out_size) {
    const int*   tokens = (const int*)d_in[0];
    const int*   plen   = (const int*)d_in[1];
    const float* E      = (const float*)d_in[2];
    const float* en_g   = (const float*)d_in[3];
    const float* en_b   = (const float*)d_in[4];
    const float* fn_g   = (const float*)d_in[5];
    const float* fn_b   = (const float*)d_in[6];
    const float* q_w    = (const float*)d_in[7];
    const float* q_b    = (const float*)d_in[8];
    const float* k_w    = (const float*)d_in[9];
    const float* k_b    = (const float*)d_in[10];
    const float* g_w    = (const float*)d_in[11];
    const float* g_b    = (const float*)d_in[12];

    const long long lm_sz   = (long long)BB * LL * VOCAB;
    const long long gate_sz = (long long)BB * LL;
    const long long attn_sz = (long long)BB * LL * LL;
    int has_gate = (out_size >= lm_sz + gate_sz) ? 1 : 0;
    int has_attn = (out_size >= lm_sz + gate_sz + attn_sz) ? 1 : 0;

    k_hn   <<<40, 256>>>(tokens, plen, E, en_g, en_b, fn_g, fn_b);
    k_gemm <<<49 * 2, 256>>>(E, q_w, q_b, k_w, k_b, g_w, g_b);
    k_sm   <<<VOCAB, 256>>>();
    k_write<<<dim3(LL / 16, BB), 256>>>(tokens, plen, (float*)d_out, has_gate, has_attn);
}

// round 10
// speedup vs baseline: 1.1827x; 1.1827x over previous
#include <cuda_runtime.h>
#include <cstdint>

#define VOCAB 256
#define D 512
#define A 64
#define BB 8
#define LL 2048
#define LN_EPS 1e-5f

// ---------------- scratch (device globals; no allocations) ----------------
__device__ float4 g_h4[VOCAB * 128];       // h row-major: [v][d/4]
__device__ float g_q[VOCAB * A];
__device__ float g_kT[A * VOCAB];
__device__ float g_gate[VOCAB];
__device__ float g_logit[VOCAB * VOCAB];
__device__ float g_vprob[VOCAB * VOCAB];
__device__ float g_score[VOCAB * VOCAB];
__device__ float g_cnt[BB * VOCAB];

// ---------------- reduction helpers ----------------
__device__ __forceinline__ float warpSum(float v) {
    #pragma unroll
    for (int o = 16; o > 0; o >>= 1) v += __shfl_xor_sync(0xFFFFFFFFu, v, o);
    return v;
}
__device__ __forceinline__ float warpMax(float v) {
    #pragma unroll
    for (int o = 16; o > 0; o >>= 1) v = fmaxf(v, __shfl_xor_sync(0xFFFFFFFFu, v, o));
    return v;
}
__device__ __forceinline__ float blockSum256(float v, float* sh) {
    int w = threadIdx.x >> 5, l = threadIdx.x & 31;
    v = warpSum(v);
    if (l == 0) sh[w] = v;
    __syncthreads();
    if (w == 0) {
        float x = (l < 8) ? sh[l] : 0.f;
        x = warpSum(x);
        if (l == 0) sh[0] = x;
    }
    __syncthreads();
    float r = sh[0];
    __syncthreads();
    return r;
}
__device__ __forceinline__ float blockMax256(float v, float* sh) {
    int w = threadIdx.x >> 5, l = threadIdx.x & 31;
    v = warpMax(v);
    if (l == 0) sh[w] = v;
    __syncthreads();
    if (w == 0) {
        float x = (l < 8) ? sh[l] : -1e30f;
        x = warpMax(x);
        if (l == 0) sh[0] = x;
    }
    __syncthreads();
    float r = sh[0];
    __syncthreads();
    return r;
}

// ---------------- k_hn: histogram (blocks 0-7) + LN once (blocks 8-39) ----
__global__ void __launch_bounds__(256)
k_hn(const int* __restrict__ tokens, const int* __restrict__ plen,
     const float* __restrict__ E,
     const float* __restrict__ eg, const float* __restrict__ eb,
     const float* __restrict__ fg, const float* __restrict__ fb) {
    int tid = threadIdx.x, w = tid >> 5, l = tid & 31;

    if (blockIdx.x < 8) {
        int b = blockIdx.x;
        __shared__ int c[VOCAB];
        c[tid] = 0;
        __syncthreads();
        int P = plen[b];
        #pragma unroll
        for (int it = 0; it < 8; it++) {
            int i = it * 256 + tid;
            int tk = tokens[b * LL + i];
            if (i < P && tk != 0) atomicAdd(&c[tk & 255], 1);
        }
        __syncthreads();
        g_cnt[b * VOCAB + tid] = (float)c[tid];
        return;
    }

    // LN for row v = (blk-8)*8 + w, stored row-major (coalesced float4)
    int v = (blockIdx.x - 8) * 8 + w;
    const float4* E4 = (const float4*)E;
    float4 ef[4];
    #pragma unroll
    for (int j = 0; j < 4; j++) ef[j] = E4[v * 128 + l + 32 * j];
    float s = 0.f;
    #pragma unroll
    for (int j = 0; j < 4; j++) s += ef[j].x + ef[j].y + ef[j].z + ef[j].w;
    float mu = warpSum(s) * (1.f / D);
    float vv = 0.f;
    #pragma unroll
    for (int j = 0; j < 4; j++) {
        ef[j].x -= mu; ef[j].y -= mu; ef[j].z -= mu; ef[j].w -= mu;
        vv += ef[j].x * ef[j].x + ef[j].y * ef[j].y
            + ef[j].z * ef[j].z + ef[j].w * ef[j].w;
    }
    float inv = rsqrtf(warpSum(vv) * (1.f / D) + LN_EPS);
    {
        const float4* G = (const float4*)eg;
        const float4* Bv = (const float4*)eb;
        #pragma unroll
        for (int j = 0; j < 4; j++) {
            float4 g4 = G[l + 32 * j], b4 = Bv[l + 32 * j];
            ef[j].x = ef[j].x * inv * g4.x + b4.x;
            ef[j].y = ef[j].y * inv * g4.y + b4.y;
            ef[j].z = ef[j].z * inv * g4.z + b4.z;
            ef[j].w = ef[j].w * inv * g4.w + b4.w;
        }
    }
    s = 0.f;
    #pragma unroll
    for (int j = 0; j < 4; j++) s += ef[j].x + ef[j].y + ef[j].z + ef[j].w;
    mu = warpSum(s) * (1.f / D);
    vv = 0.f;
    #pragma unroll
    for (int j = 0; j < 4; j++) {
        ef[j].x -= mu; ef[j].y -= mu; ef[j].z -= mu; ef[j].w -= mu;
        vv += ef[j].x * ef[j].x + ef[j].y * ef[j].y
            + ef[j].z * ef[j].z + ef[j].w * ef[j].w;
    }
    inv = rsqrtf(warpSum(vv) * (1.f / D) + LN_EPS);
    {
        const float4* G = (const float4*)fg;
        const float4* Bv = (const float4*)fb;
        #pragma unroll
        for (int j = 0; j < 4; j++) {
            float4 g4 = G[l + 32 * j], b4 = Bv[l + 32 * j];
            float4 hv;
            hv.x = ef[j].x * inv * g4.x + b4.x;
            hv.y = ef[j].y * inv * g4.y + b4.y;
            hv.z = ef[j].z * inv * g4.z + b4.z;
            hv.w = ef[j].w * inv * g4.w + b4.w;
            g_h4[v * 128 + l + 32 * j] = hv;   // row-major, coalesced
        }
    }
}

// ---------------- k_proj: 800 blocks, loads h tile coalesced --------------
// proj block pb: v-rows (pb%32)*8.. , o-cols (pb/32)*16..
// output column o: [0,256) logits, [256,320) q, [320,384) kT, 384 gate
__global__ void __launch_bounds__(256)
k_proj(const float* __restrict__ E,
       const float* __restrict__ qw, const float* __restrict__ qb,
       const float* __restrict__ kw, const float* __restrict__ kb,
       const float* __restrict__ gw, const float* __restrict__ gb) {
    int tid = threadIdx.x, w = tid >> 5, l = tid & 31;
    int pb = blockIdx.x;
    int v0 = (pb & 31) * 8;
    int obase = (pb >> 5) * 16;
    __shared__ __align__(16) float4 hs4[8 * 128];

    // ---- per-warp setup: 2 output columns; weight loads issued first ----
    int olist[2];
    bool oval[2];
    float bias[2];
    const float4* wrow4[2];
    #pragma unroll
    for (int oi = 0; oi < 2; oi++) {
        int o = obase + w * 2 + oi;
        oval[oi] = (o <= 384);
        int oe = oval[oi] ? o : 384;
        olist[oi] = oe;
        const float* wr;
        if (oe < 256)      { wr = E + oe * D;          bias[oi] = 0.f; }
        else if (oe < 320) { wr = qw + (oe - 256) * D; bias[oi] = qb[oe - 256]; }
        else if (oe < 384) { wr = kw + (oe - 320) * D; bias[oi] = kb[oe - 320]; }
        else               { wr = gw;                  bias[oi] = gb[0]; }
        wrow4[oi] = (const float4*)wr;
    }
    float4 e4[2][4];
    #pragma unroll
    for (int oi = 0; oi < 2; oi++)
        #pragma unroll
        for (int jj = 0; jj < 4; jj++)
            e4[oi][jj] = wrow4[oi][l + 32 * jj];

    // ---- h tile: 8 rows, coalesced float4 load from g_h4 ----
    #pragma unroll
    for (int i = 0; i < 4; i++)
        hs4[tid + 256 * i] = g_h4[v0 * 128 + tid + 256 * i];
    __syncthreads();

    // ---- projections: 8 v-rows x 2 o's, register-blocked ----
    float acc[8][2];
    #pragma unroll
    for (int r = 0; r < 8; r++) { acc[r][0] = 0.f; acc[r][1] = 0.f; }

    #pragma unroll
    for (int r = 0; r < 8; r++) {
        #pragma unroll
        for (int jj = 0; jj < 4; jj++) {
            float4 h4 = hs4[r * 128 + l + 32 * jj];
            #pragma unroll
            for (int oi = 0; oi < 2; oi++) {
                acc[r][oi] += e4[oi][jj].x * h4.x + e4[oi][jj].y * h4.y
                            + e4[oi][jj].z * h4.z + e4[oi][jj].w * h4.w;
            }
        }
    }

    #pragma unroll
    for (int oi = 0; oi < 2; oi++) {
        #pragma unroll
        for (int r = 0; r < 8; r++) {
            float s = warpSum(acc[r][oi]);
            if (l == 0 && oval[oi]) {
                int o = olist[oi];
                int v = v0 + r;
                if (o < 256)      g_logit[v * VOCAB + o] = s;
                else if (o < 320) g_q[v * A + (o - 256)] = s + bias[oi];
                else if (o < 384) g_kT[(o - 320) * VOCAB + v] = s + bias[oi];
                else              g_gate[v] = 1.f / (1.f + __expf(-(s + bias[oi])));
            }
        }
    }
}

// ---------------- k_sm: vocab softmax + score row per qv ------------------
__global__ void __launch_bounds__(256)
k_sm() {
    int qv = blockIdx.x, tid = threadIdx.x;
    __shared__ float red[8];
    __shared__ float qs[A];
    float lo = g_logit[qv * VOCAB + tid];
    if (tid < A) qs[tid] = g_q[qv * A + tid];
    __syncthreads();                 // qs visible to ALL warps before reading
    float s = 0.f;
    #pragma unroll
    for (int d = 0; d < A; d++) s += qs[d] * g_kT[d * VOCAB + tid];
    g_score[qv * VOCAB + tid] = s * 0.125f;
    float m = blockMax256(lo, red);
    float e = __expf(lo - m);
    float Z = blockSum256(e, red);
    g_vprob[qv * VOCAB + tid] = e * __frcp_rn(Z);
}

// ---------------- k_write: AT/LM compute + streaming writer ---------------
// 512 threads, 32 rows per block, grid (LL/32, BB)
__global__ void __launch_bounds__(512)
k_write(const int* __restrict__ tokens, const int* __restrict__ plen,
        float* __restrict__ out, int has_gate, int has_attn) {
    int b = blockIdx.y, t0 = blockIdx.x * 32, tid = threadIdx.x;
    int w = tid >> 5, l = tid & 31;
    __shared__ __align__(16) int toks[LL];
    __shared__ float lut[32][VOCAB];
    __shared__ float scnt[VOCAB];
    __shared__ int qvs[32];

    if (tid < VOCAB) scnt[tid] = g_cnt[b * VOCAB + tid];
    ((int4*)toks)[tid] = ((const int4*)(tokens + b * LL))[tid];
    __syncthreads();
    if (tid < 32) qvs[tid] = toks[t0 + tid] & 255;
    __syncthreads();

    // ---- AT rows: warp w computes rows w and w+16 (shuffles only) ----
    #pragma unroll
    for (int jj = 0; jj < 2; jj++) {
        int j = w + jj * 16;
        int qv = qvs[j];
        float sv[8], cf[8];
        float mx = -1e30f;
        #pragma unroll
        for (int m = 0; m < 8; m++) {
            int v = l + 32 * m;
            sv[m] = g_score[qv * VOCAB + v];
            cf[m] = scnt[v];
            mx = fmaxf(mx, cf[m] > 0.f ? sv[m] : -1e30f);
        }
        mx = warpMax(mx);
        float ex[8], z = 0.f;
        #pragma unroll
        for (int m = 0; m < 8; m++) {
            ex[m] = __expf(sv[m] - mx);
            z += cf[m] * ex[m];
        }
        z = warpSum(z);
        float invz = __frcp_rn(z);
        #pragma unroll
        for (int m = 0; m < 8; m++) {
            int v = l + 32 * m;
            float at = ex[m] * invz;
            if (v == 0) at = 0.f;            // PAD column masked
            lut[j][v] = at;
        }
    }
    __syncthreads();

    int P = plen[b];
    float* out_lm   = out;
    float* out_gate = out + (size_t)BB * LL * VOCAB;
    float* out_attn = out_gate + (size_t)BB * LL;

    if (has_gate && tid < 32) out_gate[b * LL + t0 + tid] = g_gate[qvs[tid]];

    // ---- LM: half = rows 0-15 / 16-31, col = tid&255 ----
    {
        int half = tid >> 8, col = tid & 255;
        float cn = scnt[col];
        #pragma unroll
        for (int jj = 0; jj < 16; jj++) {
            int j = half * 16 + jj;
            int qv = qvs[j];
            float gt = g_gate[qv];
            float pv = g_vprob[qv * VOCAB + col];
            float mixed = gt * pv + (1.f - gt) * (cn * lut[j][col]);
            __stcs(out_lm + ((size_t)(b * LL + t0 + j)) * VOCAB + col,
                   __logf(fmaxf(mixed, 1e-12f)));
        }
    }

    // ---- attn streaming: one float4 per thread per row ----
    if (has_attn) {
        int sb = tid * 4;
        int4 tk = *(const int4*)&toks[sb];
        bool m0 = sb + 0 < P, m1 = sb + 1 < P, m2 = sb + 2 < P, m3 = sb + 3 < P;
        int v0 = tk.x & 255, v1 = tk.y & 255, v2 = tk.z & 255, v3 = tk.w & 255;
        #pragma unroll
        for (int j = 0; j < 32; j++) {
            float4 o;
            o.x = m0 ? lut[j][v0] : 0.f;
            o.y = m1 ? lut[j][v1] : 0.f;
            o.z = m2 ? lut[j][v2] : 0.f;
            o.w = m3 ? lut[j][v3] : 0.f;
            __stcs((float4*)(out_attn + ((size_t)(b * LL + t0 + j)) * LL) + tid, o);
        }
    }
}

// ---------------- launch ----------------
extern "C" void kernel_launch(void* const* d_in, const int* in_sizes, int n_in,
                              void* d_out, int out_size) {
    const int*   tokens = (const int*)d_in[0];
    const int*   plen   = (const int*)d_in[1];
    const float* E      = (const float*)d_in[2];
    const float* en_g   = (const float*)d_in[3];
    const float* en_b   = (const float*)d_in[4];
    const float* fn_g   = (const float*)d_in[5];
    const float* fn_b   = (const float*)d_in[6];
    const float* q_w    = (const float*)d_in[7];
    const float* q_b    = (const float*)d_in[8];
    const float* k_w    = (const float*)d_in[9];
    const float* k_b    = (const float*)d_in[10];
    const float* g_w    = (const float*)d_in[11];
    const float* g_b    = (const float*)d_in[12];

    const long long lm_sz   = (long long)BB * LL * VOCAB;
    const long long gate_sz = (long long)BB * LL;
    const long long attn_sz = (long long)BB * LL * LL;
    int has_gate = (out_size >= lm_sz + gate_sz) ? 1 : 0;
    int has_attn = (out_size >= lm_sz + gate_sz + attn_sz) ? 1 : 0;

    k_hn   <<<40, 256>>>(tokens, plen, E, en_g, en_b, fn_g, fn_b);
    k_proj <<<25 * 32, 256>>>(E, q_w, q_b, k_w, k_b, g_w, g_b);
    k_sm   <<<VOCAB, 256>>>();
    k_write<<<dim3(LL / 32, BB), 512>>>(tokens, plen, (float*)d_out, has_gate, has_attn);
}